// round 14
// baseline (speedup 1.0000x reference)
#include <cuda_runtime.h>
#include <cuda_fp16.h>
#include <math_constants.h>
#include <cstdint>

// ---------------------------------------------------------------------------
// Problem constants
// ---------------------------------------------------------------------------
#define B_DIM 4
#define T_DIM 2048
#define C_DIM 1024
#define H_DIM 16
#define D_DIM 64
#define M_ROWS (B_DIM * T_DIM)       // 8192
#define N_QKV  (3 * C_DIM)           // 3072

// ---------------------------------------------------------------------------
// Device scratch (allocation-free rule)
// ---------------------------------------------------------------------------
__device__ __half g_qkvh[(size_t)M_ROWS * N_QKV];   // qkv fp16 (Q scaled by 0.125*log2e)
__device__ __half g_xh[(size_t)M_ROWS * C_DIM];     // x fp16
__device__ __half g_wt[(size_t)N_QKV * C_DIM];      // w_attn^T fp16 [3072][1024]
__device__ __half g_wpt[(size_t)C_DIM * C_DIM];     // w_proj^T fp16 [1024][1024]
__device__ __half g_ath[(size_t)M_ROWS * C_DIM];    // attn out fp16

// ---------------------------------------------------------------------------
// Helpers
// ---------------------------------------------------------------------------
__device__ __forceinline__ uint32_t smem_u32(const void* p) {
    uint32_t a;
    asm("{ .reg .u64 t; cvta.to.shared.u64 t, %1; cvt.u32.u64 %0, t; }"
        : "=r"(a) : "l"(p));
    return a;
}

__device__ __forceinline__ void cp16(uint32_t dst, const void* src) {
    asm volatile("cp.async.cg.shared.global [%0], [%1], 16;"
                 :: "r"(dst), "l"(src));
}
#define CP_COMMIT() asm volatile("cp.async.commit_group;" ::: "memory")
#define CP_WAIT(n)  asm volatile("cp.async.wait_group %0;" :: "n"(n) : "memory")

__device__ __forceinline__ void ldsm4(uint32_t* r, uint32_t addr) {
    asm volatile("ldmatrix.sync.aligned.m8n8.x4.shared.b16 {%0,%1,%2,%3}, [%4];"
                 : "=r"(r[0]), "=r"(r[1]), "=r"(r[2]), "=r"(r[3]) : "r"(addr));
}

__device__ __forceinline__ void ldsm4t(uint32_t* r, uint32_t addr) {
    asm volatile("ldmatrix.sync.aligned.m8n8.x4.trans.shared.b16 {%0,%1,%2,%3}, [%4];"
                 : "=r"(r[0]), "=r"(r[1]), "=r"(r[2]), "=r"(r[3]) : "r"(addr));
}

__device__ __forceinline__ void mma16816(float* c, const uint32_t* a,
                                         const uint32_t* b) {
    asm volatile(
        "mma.sync.aligned.m16n8k16.row.col.f32.f16.f16.f32 "
        "{%0,%1,%2,%3}, {%4,%5,%6,%7}, {%8,%9}, {%0,%1,%2,%3};"
        : "+f"(c[0]), "+f"(c[1]), "+f"(c[2]), "+f"(c[3])
        : "r"(a[0]), "r"(a[1]), "r"(a[2]), "r"(a[3]), "r"(b[0]), "r"(b[1]));
}

// exp2 of a float pair -> packed fp16x2 via MUFU ex2.approx.f16x2
__device__ __forceinline__ uint32_t ex2h2(float x, float y) {
    __half2 h = __floats2half2_rn(x, y);
    uint32_t u = *reinterpret_cast<uint32_t*>(&h);
    uint32_t r;
    asm volatile("ex2.approx.f16x2 %0, %1;" : "=r"(r) : "r"(u));
    return r;
}

// exp2 fp32 (single MUFU op)
__device__ __forceinline__ float fexp2(float x) {
    float r;
    asm volatile("ex2.approx.f32 %0, %1;" : "=f"(r) : "f"(x));
    return r;
}

// ---------------------------------------------------------------------------
// Prep kernels
// ---------------------------------------------------------------------------
__global__ void k_half(const float* __restrict__ in,
                       __half* __restrict__ outp, int n)
{
    int i = (blockIdx.x * blockDim.x + threadIdx.x) * 4;
    if (i >= n) return;
    float4 v = *(const float4*)(in + i);
    *(__half2*)(outp + i)     = __floats2half2_rn(v.x, v.y);
    *(__half2*)(outp + i + 2) = __floats2half2_rn(v.z, v.w);
}

// W[K][N] row-major -> T[N][K] fp16 (single)
__global__ void k_transpose_half(const float* __restrict__ W,
                                 __half* __restrict__ T, int K, int N)
{
    __shared__ float tile[32][33];
    const int k0 = blockIdx.y * 32;
    const int n0 = blockIdx.x * 32;
    const int tx = threadIdx.x;
    const int ty = threadIdx.y;
#pragma unroll
    for (int r = 0; r < 4; ++r)
        tile[ty + r * 8][tx] = W[(size_t)(k0 + ty + r * 8) * N + n0 + tx];
    __syncthreads();
#pragma unroll
    for (int r = 0; r < 4; ++r) {
        float v = tile[tx][ty + r * 8];
        T[(size_t)(n0 + ty + r * 8) * K + k0 + tx] = __float2half(v);
    }
}

// ---------------------------------------------------------------------------
// Unified 1-product HMMA GEMM: C = A @ Bt^T + bias.
// 128x128 CTA tile, BK=64, 8 warps (32x64), 3-stage ring, one barrier per
// chunk (16 chunks for K=1024), 2 CTAs/SM.
// QKV_OUT: fp16 out, Q columns (col < C_DIM) scaled by 0.125*log2e;
// else fp32 out.
// ---------------------------------------------------------------------------
#define BKC  64
#define LDSB 144                      // 128B row + 16B pad (conflict-free ldsm)
#define TILE (128 * LDSB)             // 18432 per operand tile
#define STG  (2 * TILE)               // 36864 per stage (A, B)
#define NSTG 3
#define GEMM_SMEM (NSTG * STG)        // 110592 -> 2 CTAs/SM (221KB of 228KB)
#define QSCALE 0.18033688f            // 0.125 * log2(e)

template<bool QKV_OUT>
__global__ void __launch_bounds__(256, 2)
gemm_1p(const __half* __restrict__ A, const __half* __restrict__ Bf,
        const float* __restrict__ bias, float* __restrict__ Cf,
        __half* __restrict__ Ch, int N, int K)
{
    extern __shared__ char sm[];
    const uint32_t sbase = smem_u32(sm);

    const int tid  = threadIdx.x;
    const int lane = tid & 31;
    const int wid  = tid >> 5;
    const int m0 = blockIdx.y * 128;
    const int n0 = blockIdx.x * 128;
    const int wm = (wid & 3) * 32;
    const int wn = (wid >> 2) * 64;

    float acc[2][8][4];
#pragma unroll
    for (int i = 0; i < 2; ++i)
#pragma unroll
        for (int j = 0; j < 8; ++j)
#pragma unroll
            for (int k = 0; k < 4; ++k) acc[i][j][k] = 0.0f;

    // loader: 128 rows x 128B per tile; 2 threads/row, 4 x 16B slots each
    const int lr = tid >> 1;               // 0..127
    const int lc = (tid & 1) * 4;          // slot base 0 or 4
    const __half* pA = A + (size_t)(m0 + lr) * K + lc * 8;
    const __half* pB = Bf + (size_t)(n0 + lr) * K + lc * 8;
    const uint32_t dD = (uint32_t)lr * LDSB + (uint32_t)lc * 16;

    auto load_chunk = [&](int c, int buf) {
        const int koff = c * BKC;
        const uint32_t db = sbase + buf * STG;
#pragma unroll
        for (int s = 0; s < 4; ++s) {
            cp16(db + dD + s * 16,        pA + koff + s * 8);
            cp16(db + TILE + dD + s * 16, pB + koff + s * 8);
        }
        CP_COMMIT();
    };

    const int NC = K / BKC;               // 16
    load_chunk(0, 0);
    load_chunk(1, 1);

    int buf = 0;
    for (int c = 0; c < NC; ++c) {
        if (c + 1 < NC) { CP_WAIT(1); } else { CP_WAIT(0); }
        __syncthreads();
        if (c + 2 < NC) {
            int nb = buf + 2; if (nb >= NSTG) nb -= NSTG;
            load_chunk(c + 2, nb);
        }

        const uint32_t tb = sbase + buf * STG;
#pragma unroll
        for (int ks = 0; ks < 4; ++ks) {
            uint32_t ah[2][4];
#pragma unroll
            for (int mi = 0; mi < 2; ++mi) {
                uint32_t off = (uint32_t)(wm + mi * 16 + (lane & 15)) * LDSB
                             + ks * 32 + (lane >> 4) * 16;
                ldsm4(ah[mi], tb + off);
            }
#pragma unroll
            for (int np = 0; np < 4; ++np) {
                uint32_t bf[4];
                uint32_t off = (uint32_t)(wn + np * 16 + (lane & 7)
                             + ((lane >> 4) & 1) * 8) * LDSB
                             + ks * 32 + ((lane >> 3) & 1) * 16;
                ldsm4(bf, tb + TILE + off);
#pragma unroll
                for (int mi = 0; mi < 2; ++mi)
#pragma unroll
                    for (int nj = 0; nj < 2; ++nj)
                        mma16816(acc[mi][2 * np + nj], ah[mi], &bf[nj * 2]);
            }
        }
        if (++buf >= NSTG) buf -= NSTG;
    }

#pragma unroll
    for (int mi = 0; mi < 2; ++mi) {
        const int row = m0 + wm + mi * 16 + (lane >> 2);
#pragma unroll
        for (int ni = 0; ni < 8; ++ni) {
            const int col = n0 + wn + ni * 8 + (lane & 3) * 2;
            float v0x = acc[mi][ni][0] + bias[col];
            float v0y = acc[mi][ni][1] + bias[col + 1];
            float v1x = acc[mi][ni][2] + bias[col];
            float v1y = acc[mi][ni][3] + bias[col + 1];
            if (QKV_OUT) {
                if (col < C_DIM) {     // Q: scale by 1/sqrt(D)*log2e
                    v0x *= QSCALE; v0y *= QSCALE;
                    v1x *= QSCALE; v1y *= QSCALE;
                }
                *(__half2*)(Ch + (size_t)row * N + col) =
                    __floats2half2_rn(v0x, v0y);
                *(__half2*)(Ch + (size_t)(row + 8) * N + col) =
                    __floats2half2_rn(v1x, v1y);
            } else {
                float2 v0, v1;
                v0.x = v0x; v0.y = v0y;
                v1.x = v1x; v1.y = v1y;
                *(float2*)(Cf + (size_t)row * N + col)       = v0;
                *(float2*)(Cf + (size_t)(row + 8) * N + col) = v1;
            }
        }
    }
}

// ---------------------------------------------------------------------------
// HMMA causal flash attention, log2-domain softmax, single-fp16 throughout.
// P via ex2.approx.f16x2; row sums via ones-MMA; fp16 output (no lo).
// 3-stage K/V ring, one barrier/tile, 2 CTAs/SM.
// ---------------------------------------------------------------------------
#define FA_BQ   128
#define FA_BC   64
#define FA_LDB  144
#define FA_BUF  (FA_BQ * FA_LDB)         // 18432: Q
#define FA_TILE (FA_BC * FA_LDB)         // 9216
#define FA_BUFSZ (2 * FA_TILE)           // 18432 (K, V)
#define FA_NSTG 3
#define FA_SMEM (FA_BUF + FA_NSTG * FA_BUFSZ)  // 73728
#define NEG_BIG (-1e30f)
#define ONE_H2  0x3C003C00u              // half2(1.0, 1.0)

__global__ void __launch_bounds__(256, 2)
flash_mma(const __half* __restrict__ qkv, __half* __restrict__ ath)
{
    extern __shared__ char fsm[];
    const uint32_t sb = smem_u32(fsm);

    const int tid  = threadIdx.x;
    const int lane = tid & 31;
    const int wid  = tid >> 5;
    const int b = blockIdx.x >> 4;
    const int h = blockIdx.x & 15;
    const int yy = (int)gridDim.y - 1 - (int)blockIdx.y;   // heavy tiles first
    const int q0 = yy * FA_BQ;
    const int NT = 2 * (yy + 1);
    const int bT = b * T_DIM;
    const int hoff = h * D_DIM;

    auto load_tile = [&](int t, int bufi) {
        const int k0 = t * FA_BC;
        const int row = tid >> 2;
        const int ch2 = (tid & 3) * 2;
        const size_t rb = (size_t)(bT + k0 + row) * N_QKV + hoff;
        const uint32_t tb = sb + FA_BUF + bufi * FA_BUFSZ;
        const uint32_t d = tb + row * FA_LDB + ch2 * 16;
        const __half* skh = qkv + rb + C_DIM;
        const __half* svh = qkv + rb + 2 * C_DIM;
        cp16(d + 0 * FA_TILE,      skh + ch2 * 8);
        cp16(d + 0 * FA_TILE + 16, skh + ch2 * 8 + 8);
        cp16(d + 1 * FA_TILE,      svh + ch2 * 8);
        cp16(d + 1 * FA_TILE + 16, svh + ch2 * 8 + 8);
        CP_COMMIT();
    };

    // ---- issue Q tile load, then prefetch K/V tiles 0 & 1 ----
#pragma unroll
    for (int i = 0; i < 4; ++i) {
        int idx = tid + i * 256;          // 0..1023
        int row = idx >> 3;
        int ch  = idx & 7;
        const __half* src = qkv + (size_t)(bT + q0 + row) * N_QKV + hoff + ch * 8;
        cp16(sb + row * FA_LDB + ch * 16, src);
    }
    CP_COMMIT();
    load_tile(0, 0);
    load_tile(1, 1);          // NT >= 2 always

    CP_WAIT(2);               // Q done; K/V tiles may still be in flight
    __syncthreads();

    uint32_t qf[4][4];
#pragma unroll
    for (int ks = 0; ks < 4; ++ks) {
        uint32_t off = (uint32_t)(wid * 16 + (lane & 15)) * FA_LDB
                     + ks * 32 + (lane >> 4) * 16;
        ldsm4(qf[ks], sb + off);
    }

    float o[8][4];
#pragma unroll
    for (int i = 0; i < 8; ++i)
#pragma unroll
        for (int j = 0; j < 4; ++j) o[i][j] = 0.0f;
    float la[4] = {0.0f, 0.0f, 0.0f, 0.0f};       // l via ones-MMA
    float m0 = NEG_BIG, m1 = NEG_BIG;
    const int qr  = q0 + wid * 16;
    const int qp0 = qr + (lane >> 2);
    const int qp1 = qp0 + 8;
    const uint32_t ones[2] = {ONE_H2, ONE_H2};

    int buf = 0;
    for (int t = 0; t < NT; ++t) {
        if (t + 1 < NT) { CP_WAIT(1); } else { CP_WAIT(0); }
        __syncthreads();
        if (t + 2 < NT) {
            int nb = buf + 2; if (nb >= FA_NSTG) nb -= FA_NSTG;
            load_tile(t + 2, nb);
        }

        const int k0 = t * FA_BC;
        if (k0 <= qr + 15) {
            const uint32_t tb = sb + FA_BUF + buf * FA_BUFSZ;

            float s[8][4];
#pragma unroll
            for (int i = 0; i < 8; ++i)
#pragma unroll
                for (int j = 0; j < 4; ++j) s[i][j] = 0.0f;

#pragma unroll
            for (int ks = 0; ks < 4; ++ks) {
                uint32_t kh[4][4];
#pragma unroll
                for (int np = 0; np < 4; ++np) {
                    uint32_t off = (uint32_t)(np * 16 + (lane & 7)
                                 + ((lane >> 4) & 1) * 8) * FA_LDB
                                 + ks * 32 + ((lane >> 3) & 1) * 16;
                    ldsm4(kh[np], tb + 0 * FA_TILE + off);
                }
#pragma unroll
                for (int ni = 0; ni < 8; ++ni)
                    mma16816(s[ni], qf[ks], &kh[ni >> 1][(ni & 1) * 2]);
            }

            // causal mask (s already in log2 units)
            if (k0 + FA_BC - 1 > qr) {
#pragma unroll
                for (int ni = 0; ni < 8; ++ni) {
                    int kp = k0 + ni * 8 + 2 * (lane & 3);
                    if (kp     > qp0) s[ni][0] = NEG_BIG;
                    if (kp + 1 > qp0) s[ni][1] = NEG_BIG;
                    if (kp     > qp1) s[ni][2] = NEG_BIG;
                    if (kp + 1 > qp1) s[ni][3] = NEG_BIG;
                }
            }

            float mx0 = NEG_BIG, mx1 = NEG_BIG;
#pragma unroll
            for (int ni = 0; ni < 8; ++ni) {
                mx0 = fmaxf(mx0, fmaxf(s[ni][0], s[ni][1]));
                mx1 = fmaxf(mx1, fmaxf(s[ni][2], s[ni][3]));
            }
            mx0 = fmaxf(mx0, __shfl_xor_sync(0xffffffffu, mx0, 1));
            mx0 = fmaxf(mx0, __shfl_xor_sync(0xffffffffu, mx0, 2));
            mx1 = fmaxf(mx1, __shfl_xor_sync(0xffffffffu, mx1, 1));
            mx1 = fmaxf(mx1, __shfl_xor_sync(0xffffffffu, mx1, 2));
            const float m0n = fmaxf(m0, mx0);
            const float m1n = fmaxf(m1, mx1);
            const float c0 = fexp2(m0 - m0n);     // 0 on first tile
            const float c1 = fexp2(m1 - m1n);
            la[0] *= c0; la[2] *= c1;
#pragma unroll
            for (int ni = 0; ni < 8; ++ni) {
                o[ni][0] *= c0; o[ni][1] *= c0;
                o[ni][2] *= c1; o[ni][3] *= c1;
            }
            m0 = m0n; m1 = m1n;

            // P = exp2(s - m) as fp16 fragments; l += P @ 1; O += P V
#pragma unroll
            for (int ks = 0; ks < 4; ++ks) {
                uint32_t pa[4];
                pa[0] = ex2h2(s[2*ks][0]   - m0, s[2*ks][1]   - m0);
                pa[1] = ex2h2(s[2*ks][2]   - m1, s[2*ks][3]   - m1);
                pa[2] = ex2h2(s[2*ks+1][0] - m0, s[2*ks+1][1] - m0);
                pa[3] = ex2h2(s[2*ks+1][2] - m1, s[2*ks+1][3] - m1);

                mma16816(la, pa, ones);           // row sums

                uint32_t vh[4][4];
#pragma unroll
                for (int nd = 0; nd < 4; ++nd) {
                    uint32_t off = (uint32_t)(ks * 16 + (lane & 15)) * FA_LDB
                                 + nd * 32 + (lane >> 4) * 16;
                    ldsm4t(vh[nd], tb + 1 * FA_TILE + off);
                }
#pragma unroll
                for (int ni = 0; ni < 8; ++ni)
                    mma16816(o[ni], pa, &vh[ni >> 1][(ni & 1) * 2]);
            }
        }
        if (++buf >= FA_NSTG) buf -= FA_NSTG;
    }

    // ---- epilogue: normalize + fp16 store ----
    const float i0 = 1.0f / la[0];
    const float i1 = 1.0f / la[2];

    const size_t r0o = (size_t)(bT + qp0) * C_DIM + hoff + 2 * (lane & 3);
    const size_t r1o = (size_t)(bT + qp1) * C_DIM + hoff + 2 * (lane & 3);
#pragma unroll
    for (int ni = 0; ni < 8; ++ni) {
        *(__half2*)(ath + r0o + ni * 8) =
            __floats2half2_rn(o[ni][0] * i0, o[ni][1] * i0);
        *(__half2*)(ath + r1o + ni * 8) =
            __floats2half2_rn(o[ni][2] * i1, o[ni][3] * i1);
    }
}

// ---------------------------------------------------------------------------
// Launch
// ---------------------------------------------------------------------------
extern "C" void kernel_launch(void* const* d_in, const int* in_sizes, int n_in,
                              void* d_out, int out_size)
{
    const float* x      = (const float*)d_in[0];
    const float* w_attn = (const float*)d_in[1];
    const float* b_attn = (const float*)d_in[2];
    const float* w_proj = (const float*)d_in[3];
    const float* b_proj = (const float*)d_in[4];
    float* out = (float*)d_out;

    void *p_q, *p_xh, *p_wt, *p_wpt, *p_ath;
    cudaGetSymbolAddress(&p_q,   g_qkvh);
    cudaGetSymbolAddress(&p_xh,  g_xh);
    cudaGetSymbolAddress(&p_wt,  g_wt);
    cudaGetSymbolAddress(&p_wpt, g_wpt);
    cudaGetSymbolAddress(&p_ath, g_ath);

    cudaFuncSetAttribute(gemm_1p<true>,
                         cudaFuncAttributeMaxDynamicSharedMemorySize, GEMM_SMEM);
    cudaFuncSetAttribute(gemm_1p<false>,
                         cudaFuncAttributeMaxDynamicSharedMemorySize, GEMM_SMEM);
    cudaFuncSetAttribute(flash_mma,
                         cudaFuncAttributeMaxDynamicSharedMemorySize, FA_SMEM);

    // 1) x -> fp16
    {
        int n = M_ROWS * C_DIM;
        k_half<<<n / 4 / 256, 256>>>(x, (__half*)p_xh, n);
    }
    // 2) transpose weights -> fp16
    {
        dim3 g(N_QKV / 32, C_DIM / 32);
        k_transpose_half<<<g, dim3(32, 8)>>>(w_attn, (__half*)p_wt, C_DIM, N_QKV);
    }
    {
        dim3 g(C_DIM / 32, C_DIM / 32);
        k_transpose_half<<<g, dim3(32, 8)>>>(w_proj, (__half*)p_wpt, C_DIM, C_DIM);
    }
    // 3) qkv = x @ w_attn + b_attn  (1-product fp16; Q scaled by log2e/8)
    {
        dim3 grid(N_QKV / 128, M_ROWS / 128);
        gemm_1p<true><<<grid, 256, GEMM_SMEM>>>(
            (const __half*)p_xh, (const __half*)p_wt, b_attn,
            nullptr, (__half*)p_q, N_QKV, C_DIM);
    }
    // 4) causal MHA (log2-domain flash, fp16 output)
    {
        dim3 grid(B_DIM * H_DIM, T_DIM / FA_BQ);
        flash_mma<<<grid, 256, FA_SMEM>>>((const __half*)p_q, (__half*)p_ath);
    }
    // 5) out = att @ w_proj + b_proj (1-product, fp32 out)
    {
        dim3 grid(C_DIM / 128, M_ROWS / 128);
        gemm_1p<false><<<grid, 256, GEMM_SMEM>>>(
            (const __half*)p_ath, (const __half*)p_wpt, b_proj,
            out, nullptr, C_DIM, C_DIM);
    }
}

// round 15
// speedup vs baseline: 1.1766x; 1.1766x over previous
#include <cuda_runtime.h>
#include <cuda_fp16.h>
#include <math_constants.h>
#include <cstdint>

// ---------------------------------------------------------------------------
// Problem constants
// ---------------------------------------------------------------------------
#define B_DIM 4
#define T_DIM 2048
#define C_DIM 1024
#define H_DIM 16
#define D_DIM 64
#define M_ROWS (B_DIM * T_DIM)       // 8192
#define N_QKV  (3 * C_DIM)           // 3072

// ---------------------------------------------------------------------------
// Device scratch (allocation-free rule)
// ---------------------------------------------------------------------------
__device__ __half g_qkvh[(size_t)M_ROWS * N_QKV];   // qkv fp16 (Q scaled by 0.125*log2e)
__device__ __half g_xh[(size_t)M_ROWS * C_DIM];     // x fp16
__device__ __half g_wt[(size_t)N_QKV * C_DIM];      // w_attn^T fp16 [3072][1024]
__device__ __half g_wpt[(size_t)C_DIM * C_DIM];     // w_proj^T fp16 [1024][1024]
__device__ __half g_ath[(size_t)M_ROWS * C_DIM];    // attn out fp16

// ---------------------------------------------------------------------------
// Helpers
// ---------------------------------------------------------------------------
__device__ __forceinline__ uint32_t smem_u32(const void* p) {
    uint32_t a;
    asm("{ .reg .u64 t; cvta.to.shared.u64 t, %1; cvt.u32.u64 %0, t; }"
        : "=r"(a) : "l"(p));
    return a;
}

__device__ __forceinline__ void cp16(uint32_t dst, const void* src) {
    asm volatile("cp.async.cg.shared.global [%0], [%1], 16;"
                 :: "r"(dst), "l"(src));
}
#define CP_COMMIT() asm volatile("cp.async.commit_group;" ::: "memory")
#define CP_WAIT(n)  asm volatile("cp.async.wait_group %0;" :: "n"(n) : "memory")

__device__ __forceinline__ void ldsm4(uint32_t* r, uint32_t addr) {
    asm volatile("ldmatrix.sync.aligned.m8n8.x4.shared.b16 {%0,%1,%2,%3}, [%4];"
                 : "=r"(r[0]), "=r"(r[1]), "=r"(r[2]), "=r"(r[3]) : "r"(addr));
}

__device__ __forceinline__ void ldsm4t(uint32_t* r, uint32_t addr) {
    asm volatile("ldmatrix.sync.aligned.m8n8.x4.trans.shared.b16 {%0,%1,%2,%3}, [%4];"
                 : "=r"(r[0]), "=r"(r[1]), "=r"(r[2]), "=r"(r[3]) : "r"(addr));
}

__device__ __forceinline__ void mma16816(float* c, const uint32_t* a,
                                         const uint32_t* b) {
    asm volatile(
        "mma.sync.aligned.m16n8k16.row.col.f32.f16.f16.f32 "
        "{%0,%1,%2,%3}, {%4,%5,%6,%7}, {%8,%9}, {%0,%1,%2,%3};"
        : "+f"(c[0]), "+f"(c[1]), "+f"(c[2]), "+f"(c[3])
        : "r"(a[0]), "r"(a[1]), "r"(a[2]), "r"(a[3]), "r"(b[0]), "r"(b[1]));
}

// exp2 of a float pair -> packed fp16x2 via MUFU ex2.approx.f16x2
__device__ __forceinline__ uint32_t ex2h2(float x, float y) {
    __half2 h = __floats2half2_rn(x, y);
    uint32_t u = *reinterpret_cast<uint32_t*>(&h);
    uint32_t r;
    asm volatile("ex2.approx.f16x2 %0, %1;" : "=r"(r) : "r"(u));
    return r;
}

// exp2 fp32 (single MUFU op)
__device__ __forceinline__ float fexp2(float x) {
    float r;
    asm volatile("ex2.approx.f32 %0, %1;" : "=f"(r) : "f"(x));
    return r;
}

// ---------------------------------------------------------------------------
// Prep kernels
// ---------------------------------------------------------------------------
__global__ void k_half(const float* __restrict__ in,
                       __half* __restrict__ outp, int n)
{
    int i = (blockIdx.x * blockDim.x + threadIdx.x) * 4;
    if (i >= n) return;
    float4 v = *(const float4*)(in + i);
    *(__half2*)(outp + i)     = __floats2half2_rn(v.x, v.y);
    *(__half2*)(outp + i + 2) = __floats2half2_rn(v.z, v.w);
}

// W[K][N] row-major -> T[N][K] fp16 (single)
__global__ void k_transpose_half(const float* __restrict__ W,
                                 __half* __restrict__ T, int K, int N)
{
    __shared__ float tile[32][33];
    const int k0 = blockIdx.y * 32;
    const int n0 = blockIdx.x * 32;
    const int tx = threadIdx.x;
    const int ty = threadIdx.y;
#pragma unroll
    for (int r = 0; r < 4; ++r)
        tile[ty + r * 8][tx] = W[(size_t)(k0 + ty + r * 8) * N + n0 + tx];
    __syncthreads();
#pragma unroll
    for (int r = 0; r < 4; ++r) {
        float v = tile[tx][ty + r * 8];
        T[(size_t)(n0 + ty + r * 8) * K + k0 + tx] = __float2half(v);
    }
}

// ---------------------------------------------------------------------------
// Unified 1-product HMMA GEMM (R13 geometry): C = A @ Bt^T + bias.
// 128x128 CTA tile, BK=32, 8 warps (32x64), 3-stage ring, 2 CTAs/SM.
// QKV_OUT: fp16 out, Q columns (col < C_DIM) scaled by 0.125*log2e;
// else fp32 out.
// ---------------------------------------------------------------------------
#define BKC  32
#define LDSB 80                       // smem row stride bytes
#define TILE (128 * LDSB)             // 10240 per operand tile
#define STG  (2 * TILE)               // 20480 per stage (A, B)
#define NSTG 3
#define GEMM_SMEM (NSTG * STG)        // 61440 -> 2 CTAs/SM
#define QSCALE 0.18033688f            // 0.125 * log2(e)

template<bool QKV_OUT>
__global__ void __launch_bounds__(256, 2)
gemm_1p(const __half* __restrict__ A, const __half* __restrict__ Bf,
        const float* __restrict__ bias, float* __restrict__ Cf,
        __half* __restrict__ Ch, int N, int K)
{
    extern __shared__ char sm[];
    const uint32_t sbase = smem_u32(sm);

    const int tid  = threadIdx.x;
    const int lane = tid & 31;
    const int wid  = tid >> 5;
    const int m0 = blockIdx.y * 128;
    const int n0 = blockIdx.x * 128;
    const int wm = (wid & 3) * 32;
    const int wn = (wid >> 2) * 64;

    float acc[2][8][4];
#pragma unroll
    for (int i = 0; i < 2; ++i)
#pragma unroll
        for (int j = 0; j < 8; ++j)
#pragma unroll
            for (int k = 0; k < 4; ++k) acc[i][j][k] = 0.0f;

    const int r0 = tid >> 2, c0 = tid & 3;
    const int r1 = r0 + 64;
    const __half* pA0 = A + (size_t)(m0 + r0) * K + c0 * 8;
    const __half* pA1 = A + (size_t)(m0 + r1) * K + c0 * 8;
    const __half* pB0 = Bf + (size_t)(n0 + r0) * K + c0 * 8;
    const __half* pB1 = Bf + (size_t)(n0 + r1) * K + c0 * 8;
    const uint32_t dA0 = (uint32_t)r0 * LDSB + (uint32_t)c0 * 16;
    const uint32_t dA1 = (uint32_t)r1 * LDSB + (uint32_t)c0 * 16;

    auto load_chunk = [&](int c, int buf) {
        const int koff = c * BKC;
        const uint32_t db = sbase + buf * STG;
        cp16(db + dA0, pA0 + koff);
        cp16(db + dA1, pA1 + koff);
        cp16(db + TILE + dA0, pB0 + koff);
        cp16(db + TILE + dA1, pB1 + koff);
        CP_COMMIT();
    };

    const int NC = K / BKC;
    load_chunk(0, 0);
    load_chunk(1, 1);

    int buf = 0;
    for (int c = 0; c < NC; ++c) {
        if (c + 1 < NC) { CP_WAIT(1); } else { CP_WAIT(0); }
        __syncthreads();
        if (c + 2 < NC) {
            int nb = buf + 2; if (nb >= NSTG) nb -= NSTG;
            load_chunk(c + 2, nb);
        }

        const uint32_t tb = sbase + buf * STG;
#pragma unroll
        for (int ks = 0; ks < 2; ++ks) {
            uint32_t ah[2][4];
#pragma unroll
            for (int mi = 0; mi < 2; ++mi) {
                uint32_t off = (uint32_t)(wm + mi * 16 + (lane & 15)) * LDSB
                             + ks * 32 + (lane >> 4) * 16;
                ldsm4(ah[mi], tb + off);
            }
#pragma unroll
            for (int np = 0; np < 4; ++np) {
                uint32_t bf[4];
                uint32_t off = (uint32_t)(wn + np * 16 + (lane & 7)
                             + ((lane >> 4) & 1) * 8) * LDSB
                             + ks * 32 + ((lane >> 3) & 1) * 16;
                ldsm4(bf, tb + TILE + off);
#pragma unroll
                for (int mi = 0; mi < 2; ++mi)
#pragma unroll
                    for (int nj = 0; nj < 2; ++nj)
                        mma16816(acc[mi][2 * np + nj], ah[mi], &bf[nj * 2]);
            }
        }
        if (++buf >= NSTG) buf -= NSTG;
    }

#pragma unroll
    for (int mi = 0; mi < 2; ++mi) {
        const int row = m0 + wm + mi * 16 + (lane >> 2);
#pragma unroll
        for (int ni = 0; ni < 8; ++ni) {
            const int col = n0 + wn + ni * 8 + (lane & 3) * 2;
            float v0x = acc[mi][ni][0] + bias[col];
            float v0y = acc[mi][ni][1] + bias[col + 1];
            float v1x = acc[mi][ni][2] + bias[col];
            float v1y = acc[mi][ni][3] + bias[col + 1];
            if (QKV_OUT) {
                if (col < C_DIM) {     // Q: scale by 1/sqrt(D)*log2e
                    v0x *= QSCALE; v0y *= QSCALE;
                    v1x *= QSCALE; v1y *= QSCALE;
                }
                *(__half2*)(Ch + (size_t)row * N + col) =
                    __floats2half2_rn(v0x, v0y);
                *(__half2*)(Ch + (size_t)(row + 8) * N + col) =
                    __floats2half2_rn(v1x, v1y);
            } else {
                float2 v0, v1;
                v0.x = v0x; v0.y = v0y;
                v1.x = v1x; v1.y = v1y;
                *(float2*)(Cf + (size_t)row * N + col)       = v0;
                *(float2*)(Cf + (size_t)(row + 8) * N + col) = v1;
            }
        }
    }
}

// ---------------------------------------------------------------------------
// HMMA causal flash attention, log2-domain softmax, single-fp16 throughout.
// P via ex2.approx.f16x2; row sums via ones-MMA; fp16 output (no lo).
// 3-stage K/V ring, one barrier/tile, 2 CTAs/SM.
// ---------------------------------------------------------------------------
#define FA_BQ   128
#define FA_BC   64
#define FA_LDB  144
#define FA_BUF  (FA_BQ * FA_LDB)         // 18432: Q
#define FA_TILE (FA_BC * FA_LDB)         // 9216
#define FA_BUFSZ (2 * FA_TILE)           // 18432 (K, V)
#define FA_NSTG 3
#define FA_SMEM (FA_BUF + FA_NSTG * FA_BUFSZ)  // 73728
#define NEG_BIG (-1e30f)
#define ONE_H2  0x3C003C00u              // half2(1.0, 1.0)

__global__ void __launch_bounds__(256, 2)
flash_mma(const __half* __restrict__ qkv, __half* __restrict__ ath)
{
    extern __shared__ char fsm[];
    const uint32_t sb = smem_u32(fsm);

    const int tid  = threadIdx.x;
    const int lane = tid & 31;
    const int wid  = tid >> 5;
    const int b = blockIdx.x >> 4;
    const int h = blockIdx.x & 15;
    const int yy = (int)gridDim.y - 1 - (int)blockIdx.y;   // heavy tiles first
    const int q0 = yy * FA_BQ;
    const int NT = 2 * (yy + 1);
    const int bT = b * T_DIM;
    const int hoff = h * D_DIM;

    auto load_tile = [&](int t, int bufi) {
        const int k0 = t * FA_BC;
        const int row = tid >> 2;
        const int ch2 = (tid & 3) * 2;
        const size_t rb = (size_t)(bT + k0 + row) * N_QKV + hoff;
        const uint32_t tb = sb + FA_BUF + bufi * FA_BUFSZ;
        const uint32_t d = tb + row * FA_LDB + ch2 * 16;
        const __half* skh = qkv + rb + C_DIM;
        const __half* svh = qkv + rb + 2 * C_DIM;
        cp16(d + 0 * FA_TILE,      skh + ch2 * 8);
        cp16(d + 0 * FA_TILE + 16, skh + ch2 * 8 + 8);
        cp16(d + 1 * FA_TILE,      svh + ch2 * 8);
        cp16(d + 1 * FA_TILE + 16, svh + ch2 * 8 + 8);
        CP_COMMIT();
    };

    // ---- issue Q tile load, then prefetch K/V tiles 0 & 1 ----
#pragma unroll
    for (int i = 0; i < 4; ++i) {
        int idx = tid + i * 256;          // 0..1023
        int row = idx >> 3;
        int ch  = idx & 7;
        const __half* src = qkv + (size_t)(bT + q0 + row) * N_QKV + hoff + ch * 8;
        cp16(sb + row * FA_LDB + ch * 16, src);
    }
    CP_COMMIT();
    load_tile(0, 0);
    load_tile(1, 1);          // NT >= 2 always

    CP_WAIT(2);               // Q done; K/V tiles may still be in flight
    __syncthreads();

    uint32_t qf[4][4];
#pragma unroll
    for (int ks = 0; ks < 4; ++ks) {
        uint32_t off = (uint32_t)(wid * 16 + (lane & 15)) * FA_LDB
                     + ks * 32 + (lane >> 4) * 16;
        ldsm4(qf[ks], sb + off);
    }

    float o[8][4];
#pragma unroll
    for (int i = 0; i < 8; ++i)
#pragma unroll
        for (int j = 0; j < 4; ++j) o[i][j] = 0.0f;
    float la[4] = {0.0f, 0.0f, 0.0f, 0.0f};       // l via ones-MMA
    float m0 = NEG_BIG, m1 = NEG_BIG;
    const int qr  = q0 + wid * 16;
    const int qp0 = qr + (lane >> 2);
    const int qp1 = qp0 + 8;
    const uint32_t ones[2] = {ONE_H2, ONE_H2};

    int buf = 0;
    for (int t = 0; t < NT; ++t) {
        if (t + 1 < NT) { CP_WAIT(1); } else { CP_WAIT(0); }
        __syncthreads();
        if (t + 2 < NT) {
            int nb = buf + 2; if (nb >= FA_NSTG) nb -= FA_NSTG;
            load_tile(t + 2, nb);
        }

        const int k0 = t * FA_BC;
        if (k0 <= qr + 15) {
            const uint32_t tb = sb + FA_BUF + buf * FA_BUFSZ;

            float s[8][4];
#pragma unroll
            for (int i = 0; i < 8; ++i)
#pragma unroll
                for (int j = 0; j < 4; ++j) s[i][j] = 0.0f;

#pragma unroll
            for (int ks = 0; ks < 4; ++ks) {
                uint32_t kh[4][4];
#pragma unroll
                for (int np = 0; np < 4; ++np) {
                    uint32_t off = (uint32_t)(np * 16 + (lane & 7)
                                 + ((lane >> 4) & 1) * 8) * FA_LDB
                                 + ks * 32 + ((lane >> 3) & 1) * 16;
                    ldsm4(kh[np], tb + 0 * FA_TILE + off);
                }
#pragma unroll
                for (int ni = 0; ni < 8; ++ni)
                    mma16816(s[ni], qf[ks], &kh[ni >> 1][(ni & 1) * 2]);
            }

            // causal mask (s already in log2 units)
            if (k0 + FA_BC - 1 > qr) {
#pragma unroll
                for (int ni = 0; ni < 8; ++ni) {
                    int kp = k0 + ni * 8 + 2 * (lane & 3);
                    if (kp     > qp0) s[ni][0] = NEG_BIG;
                    if (kp + 1 > qp0) s[ni][1] = NEG_BIG;
                    if (kp     > qp1) s[ni][2] = NEG_BIG;
                    if (kp + 1 > qp1) s[ni][3] = NEG_BIG;
                }
            }

            float mx0 = NEG_BIG, mx1 = NEG_BIG;
#pragma unroll
            for (int ni = 0; ni < 8; ++ni) {
                mx0 = fmaxf(mx0, fmaxf(s[ni][0], s[ni][1]));
                mx1 = fmaxf(mx1, fmaxf(s[ni][2], s[ni][3]));
            }
            mx0 = fmaxf(mx0, __shfl_xor_sync(0xffffffffu, mx0, 1));
            mx0 = fmaxf(mx0, __shfl_xor_sync(0xffffffffu, mx0, 2));
            mx1 = fmaxf(mx1, __shfl_xor_sync(0xffffffffu, mx1, 1));
            mx1 = fmaxf(mx1, __shfl_xor_sync(0xffffffffu, mx1, 2));
            const float m0n = fmaxf(m0, mx0);
            const float m1n = fmaxf(m1, mx1);
            const float c0 = fexp2(m0 - m0n);     // 0 on first tile
            const float c1 = fexp2(m1 - m1n);
            la[0] *= c0; la[2] *= c1;
#pragma unroll
            for (int ni = 0; ni < 8; ++ni) {
                o[ni][0] *= c0; o[ni][1] *= c0;
                o[ni][2] *= c1; o[ni][3] *= c1;
            }
            m0 = m0n; m1 = m1n;

            // P = exp2(s - m) as fp16 fragments; l += P @ 1; O += P V
#pragma unroll
            for (int ks = 0; ks < 4; ++ks) {
                uint32_t pa[4];
                pa[0] = ex2h2(s[2*ks][0]   - m0, s[2*ks][1]   - m0);
                pa[1] = ex2h2(s[2*ks][2]   - m1, s[2*ks][3]   - m1);
                pa[2] = ex2h2(s[2*ks+1][0] - m0, s[2*ks+1][1] - m0);
                pa[3] = ex2h2(s[2*ks+1][2] - m1, s[2*ks+1][3] - m1);

                mma16816(la, pa, ones);           // row sums

                uint32_t vh[4][4];
#pragma unroll
                for (int nd = 0; nd < 4; ++nd) {
                    uint32_t off = (uint32_t)(ks * 16 + (lane & 15)) * FA_LDB
                                 + nd * 32 + (lane >> 4) * 16;
                    ldsm4t(vh[nd], tb + 1 * FA_TILE + off);
                }
#pragma unroll
                for (int ni = 0; ni < 8; ++ni)
                    mma16816(o[ni], pa, &vh[ni >> 1][(ni & 1) * 2]);
            }
        }
        if (++buf >= FA_NSTG) buf -= FA_NSTG;
    }

    // ---- epilogue: normalize + fp16 store ----
    const float i0 = 1.0f / la[0];
    const float i1 = 1.0f / la[2];

    const size_t r0o = (size_t)(bT + qp0) * C_DIM + hoff + 2 * (lane & 3);
    const size_t r1o = (size_t)(bT + qp1) * C_DIM + hoff + 2 * (lane & 3);
#pragma unroll
    for (int ni = 0; ni < 8; ++ni) {
        *(__half2*)(ath + r0o + ni * 8) =
            __floats2half2_rn(o[ni][0] * i0, o[ni][1] * i0);
        *(__half2*)(ath + r1o + ni * 8) =
            __floats2half2_rn(o[ni][2] * i1, o[ni][3] * i1);
    }
}

// ---------------------------------------------------------------------------
// Launch
// ---------------------------------------------------------------------------
extern "C" void kernel_launch(void* const* d_in, const int* in_sizes, int n_in,
                              void* d_out, int out_size)
{
    const float* x      = (const float*)d_in[0];
    const float* w_attn = (const float*)d_in[1];
    const float* b_attn = (const float*)d_in[2];
    const float* w_proj = (const float*)d_in[3];
    const float* b_proj = (const float*)d_in[4];
    float* out = (float*)d_out;

    void *p_q, *p_xh, *p_wt, *p_wpt, *p_ath;
    cudaGetSymbolAddress(&p_q,   g_qkvh);
    cudaGetSymbolAddress(&p_xh,  g_xh);
    cudaGetSymbolAddress(&p_wt,  g_wt);
    cudaGetSymbolAddress(&p_wpt, g_wpt);
    cudaGetSymbolAddress(&p_ath, g_ath);

    cudaFuncSetAttribute(gemm_1p<true>,
                         cudaFuncAttributeMaxDynamicSharedMemorySize, GEMM_SMEM);
    cudaFuncSetAttribute(gemm_1p<false>,
                         cudaFuncAttributeMaxDynamicSharedMemorySize, GEMM_SMEM);
    cudaFuncSetAttribute(flash_mma,
                         cudaFuncAttributeMaxDynamicSharedMemorySize, FA_SMEM);

    // 1) x -> fp16
    {
        int n = M_ROWS * C_DIM;
        k_half<<<n / 4 / 256, 256>>>(x, (__half*)p_xh, n);
    }
    // 2) transpose weights -> fp16
    {
        dim3 g(N_QKV / 32, C_DIM / 32);
        k_transpose_half<<<g, dim3(32, 8)>>>(w_attn, (__half*)p_wt, C_DIM, N_QKV);
    }
    {
        dim3 g(C_DIM / 32, C_DIM / 32);
        k_transpose_half<<<g, dim3(32, 8)>>>(w_proj, (__half*)p_wpt, C_DIM, C_DIM);
    }
    // 3) qkv = x @ w_attn + b_attn  (1-product fp16; Q scaled by log2e/8)
    {
        dim3 grid(N_QKV / 128, M_ROWS / 128);
        gemm_1p<true><<<grid, 256, GEMM_SMEM>>>(
            (const __half*)p_xh, (const __half*)p_wt, b_attn,
            nullptr, (__half*)p_q, N_QKV, C_DIM);
    }
    // 4) causal MHA (log2-domain flash, fp16 output)
    {
        dim3 grid(B_DIM * H_DIM, T_DIM / FA_BQ);
        flash_mma<<<grid, 256, FA_SMEM>>>((const __half*)p_q, (__half*)p_ath);
    }
    // 5) out = att @ w_proj + b_proj (1-product, fp32 out)
    {
        dim3 grid(C_DIM / 128, M_ROWS / 128);
        gemm_1p<false><<<grid, 256, GEMM_SMEM>>>(
            (const __half*)p_ath, (const __half*)p_wpt, b_proj,
            out, nullptr, C_DIM, C_DIM);
    }
}

// round 16
// speedup vs baseline: 1.1790x; 1.0021x over previous
#include <cuda_runtime.h>
#include <cuda_fp16.h>
#include <math_constants.h>
#include <cstdint>

// ---------------------------------------------------------------------------
// Problem constants
// ---------------------------------------------------------------------------
#define B_DIM 4
#define T_DIM 2048
#define C_DIM 1024
#define H_DIM 16
#define D_DIM 64
#define M_ROWS (B_DIM * T_DIM)       // 8192
#define N_QKV  (3 * C_DIM)           // 3072

// ---------------------------------------------------------------------------
// Device scratch (allocation-free rule)
// ---------------------------------------------------------------------------
__device__ __half g_qkvh[(size_t)M_ROWS * N_QKV];   // qkv fp16 (Q scaled by 0.125*log2e)
__device__ __half g_xh[(size_t)M_ROWS * C_DIM];     // x fp16
__device__ __half g_wt[(size_t)N_QKV * C_DIM];      // w_attn^T fp16 [3072][1024]
__device__ __half g_wpt[(size_t)C_DIM * C_DIM];     // w_proj^T fp16 [1024][1024]
__device__ __half g_ath[(size_t)M_ROWS * C_DIM];    // attn out fp16

// ---------------------------------------------------------------------------
// Helpers
// ---------------------------------------------------------------------------
__device__ __forceinline__ uint32_t smem_u32(const void* p) {
    uint32_t a;
    asm("{ .reg .u64 t; cvta.to.shared.u64 t, %1; cvt.u32.u64 %0, t; }"
        : "=r"(a) : "l"(p));
    return a;
}

__device__ __forceinline__ void cp16(uint32_t dst, const void* src) {
    asm volatile("cp.async.cg.shared.global [%0], [%1], 16;"
                 :: "r"(dst), "l"(src));
}
#define CP_COMMIT() asm volatile("cp.async.commit_group;" ::: "memory")
#define CP_WAIT(n)  asm volatile("cp.async.wait_group %0;" :: "n"(n) : "memory")

__device__ __forceinline__ void ldsm4(uint32_t* r, uint32_t addr) {
    asm volatile("ldmatrix.sync.aligned.m8n8.x4.shared.b16 {%0,%1,%2,%3}, [%4];"
                 : "=r"(r[0]), "=r"(r[1]), "=r"(r[2]), "=r"(r[3]) : "r"(addr));
}

__device__ __forceinline__ void ldsm4t(uint32_t* r, uint32_t addr) {
    asm volatile("ldmatrix.sync.aligned.m8n8.x4.trans.shared.b16 {%0,%1,%2,%3}, [%4];"
                 : "=r"(r[0]), "=r"(r[1]), "=r"(r[2]), "=r"(r[3]) : "r"(addr));
}

__device__ __forceinline__ void mma16816(float* c, const uint32_t* a,
                                         const uint32_t* b) {
    asm volatile(
        "mma.sync.aligned.m16n8k16.row.col.f32.f16.f16.f32 "
        "{%0,%1,%2,%3}, {%4,%5,%6,%7}, {%8,%9}, {%0,%1,%2,%3};"
        : "+f"(c[0]), "+f"(c[1]), "+f"(c[2]), "+f"(c[3])
        : "r"(a[0]), "r"(a[1]), "r"(a[2]), "r"(a[3]), "r"(b[0]), "r"(b[1]));
}

// exp2 of a float pair -> packed fp16x2 via MUFU ex2.approx.f16x2
__device__ __forceinline__ uint32_t ex2h2(float x, float y) {
    __half2 h = __floats2half2_rn(x, y);
    uint32_t u = *reinterpret_cast<uint32_t*>(&h);
    uint32_t r;
    asm volatile("ex2.approx.f16x2 %0, %1;" : "=r"(r) : "r"(u));
    return r;
}

// exp2 fp32 (single MUFU op)
__device__ __forceinline__ float fexp2(float x) {
    float r;
    asm volatile("ex2.approx.f32 %0, %1;" : "=f"(r) : "f"(x));
    return r;
}

// ---------------------------------------------------------------------------
// Prep kernels
// ---------------------------------------------------------------------------
__global__ void k_half(const float* __restrict__ in,
                       __half* __restrict__ outp, int n)
{
    int i = (blockIdx.x * blockDim.x + threadIdx.x) * 4;
    if (i >= n) return;
    float4 v = *(const float4*)(in + i);
    *(__half2*)(outp + i)     = __floats2half2_rn(v.x, v.y);
    *(__half2*)(outp + i + 2) = __floats2half2_rn(v.z, v.w);
}

// W[K][N] row-major -> T[N][K] fp16 (single)
__global__ void k_transpose_half(const float* __restrict__ W,
                                 __half* __restrict__ T, int K, int N)
{
    __shared__ float tile[32][33];
    const int k0 = blockIdx.y * 32;
    const int n0 = blockIdx.x * 32;
    const int tx = threadIdx.x;
    const int ty = threadIdx.y;
#pragma unroll
    for (int r = 0; r < 4; ++r)
        tile[ty + r * 8][tx] = W[(size_t)(k0 + ty + r * 8) * N + n0 + tx];
    __syncthreads();
#pragma unroll
    for (int r = 0; r < 4; ++r) {
        float v = tile[tx][ty + r * 8];
        T[(size_t)(n0 + ty + r * 8) * K + k0 + tx] = __float2half(v);
    }
}

// ---------------------------------------------------------------------------
// Unified 1-product HMMA GEMM: C = A @ Bt^T + bias.
// 128x128 CTA tile, BK=32, 8 warps (32x64), 3-stage ring, 2 CTAs/SM.
// All 6 fragment ldsm batched at the top of each ks so the 32 MMAs run
// without LDS-latency stalls.
// QKV_OUT: fp16 out, Q columns (col < C_DIM) scaled by 0.125*log2e;
// else fp32 out.
// ---------------------------------------------------------------------------
#define BKC  32
#define LDSB 80                       // smem row stride bytes
#define TILE (128 * LDSB)             // 10240 per operand tile
#define STG  (2 * TILE)               // 20480 per stage (A, B)
#define NSTG 3
#define GEMM_SMEM (NSTG * STG)        // 61440 -> 2 CTAs/SM
#define QSCALE 0.18033688f            // 0.125 * log2(e)

template<bool QKV_OUT>
__global__ void __launch_bounds__(256, 2)
gemm_1p(const __half* __restrict__ A, const __half* __restrict__ Bf,
        const float* __restrict__ bias, float* __restrict__ Cf,
        __half* __restrict__ Ch, int N, int K)
{
    extern __shared__ char sm[];
    const uint32_t sbase = smem_u32(sm);

    const int tid  = threadIdx.x;
    const int lane = tid & 31;
    const int wid  = tid >> 5;
    const int m0 = blockIdx.y * 128;
    const int n0 = blockIdx.x * 128;
    const int wm = (wid & 3) * 32;
    const int wn = (wid >> 2) * 64;

    float acc[2][8][4];
#pragma unroll
    for (int i = 0; i < 2; ++i)
#pragma unroll
        for (int j = 0; j < 8; ++j)
#pragma unroll
            for (int k = 0; k < 4; ++k) acc[i][j][k] = 0.0f;

    const int r0 = tid >> 2, c0 = tid & 3;
    const int r1 = r0 + 64;
    const __half* pA0 = A + (size_t)(m0 + r0) * K + c0 * 8;
    const __half* pA1 = A + (size_t)(m0 + r1) * K + c0 * 8;
    const __half* pB0 = Bf + (size_t)(n0 + r0) * K + c0 * 8;
    const __half* pB1 = Bf + (size_t)(n0 + r1) * K + c0 * 8;
    const uint32_t dA0 = (uint32_t)r0 * LDSB + (uint32_t)c0 * 16;
    const uint32_t dA1 = (uint32_t)r1 * LDSB + (uint32_t)c0 * 16;

    auto load_chunk = [&](int c, int buf) {
        const int koff = c * BKC;
        const uint32_t db = sbase + buf * STG;
        cp16(db + dA0, pA0 + koff);
        cp16(db + dA1, pA1 + koff);
        cp16(db + TILE + dA0, pB0 + koff);
        cp16(db + TILE + dA1, pB1 + koff);
        CP_COMMIT();
    };

    const int NC = K / BKC;
    load_chunk(0, 0);
    load_chunk(1, 1);

    int buf = 0;
    for (int c = 0; c < NC; ++c) {
        if (c + 1 < NC) { CP_WAIT(1); } else { CP_WAIT(0); }
        __syncthreads();
        if (c + 2 < NC) {
            int nb = buf + 2; if (nb >= NSTG) nb -= NSTG;
            load_chunk(c + 2, nb);
        }

        const uint32_t tb = sbase + buf * STG;
#pragma unroll
        for (int ks = 0; ks < 2; ++ks) {
            uint32_t ah[2][4], bf[4][4];
            // --- batch ALL fragment loads first (hide LDS latency) ---
#pragma unroll
            for (int mi = 0; mi < 2; ++mi) {
                uint32_t off = (uint32_t)(wm + mi * 16 + (lane & 15)) * LDSB
                             + ks * 32 + (lane >> 4) * 16;
                ldsm4(ah[mi], tb + off);
            }
#pragma unroll
            for (int np = 0; np < 4; ++np) {
                uint32_t off = (uint32_t)(wn + np * 16 + (lane & 7)
                             + ((lane >> 4) & 1) * 8) * LDSB
                             + ks * 32 + ((lane >> 3) & 1) * 16;
                ldsm4(bf[np], tb + TILE + off);
            }
            // --- then the 32 MMAs, dependency-free ---
#pragma unroll
            for (int np = 0; np < 4; ++np)
#pragma unroll
                for (int mi = 0; mi < 2; ++mi)
#pragma unroll
                    for (int nj = 0; nj < 2; ++nj)
                        mma16816(acc[mi][2 * np + nj], ah[mi], &bf[np][nj * 2]);
        }
        if (++buf >= NSTG) buf -= NSTG;
    }

#pragma unroll
    for (int mi = 0; mi < 2; ++mi) {
        const int row = m0 + wm + mi * 16 + (lane >> 2);
#pragma unroll
        for (int ni = 0; ni < 8; ++ni) {
            const int col = n0 + wn + ni * 8 + (lane & 3) * 2;
            float v0x = acc[mi][ni][0] + bias[col];
            float v0y = acc[mi][ni][1] + bias[col + 1];
            float v1x = acc[mi][ni][2] + bias[col];
            float v1y = acc[mi][ni][3] + bias[col + 1];
            if (QKV_OUT) {
                if (col < C_DIM) {     // Q: scale by 1/sqrt(D)*log2e
                    v0x *= QSCALE; v0y *= QSCALE;
                    v1x *= QSCALE; v1y *= QSCALE;
                }
                *(__half2*)(Ch + (size_t)row * N + col) =
                    __floats2half2_rn(v0x, v0y);
                *(__half2*)(Ch + (size_t)(row + 8) * N + col) =
                    __floats2half2_rn(v1x, v1y);
            } else {
                float2 v0, v1;
                v0.x = v0x; v0.y = v0y;
                v1.x = v1x; v1.y = v1y;
                *(float2*)(Cf + (size_t)row * N + col)       = v0;
                *(float2*)(Cf + (size_t)(row + 8) * N + col) = v1;
            }
        }
    }
}

// ---------------------------------------------------------------------------
// HMMA causal flash attention, log2-domain softmax, single-fp16 throughout.
// P via ex2.approx.f16x2; row sums via ones-MMA; fp16 output.
// Warp-vote-gated o-rescale (skip when running max is unchanged — exact).
// 3-stage K/V ring, one barrier/tile, 2 CTAs/SM.
// ---------------------------------------------------------------------------
#define FA_BQ   128
#define FA_BC   64
#define FA_LDB  144
#define FA_BUF  (FA_BQ * FA_LDB)         // 18432: Q
#define FA_TILE (FA_BC * FA_LDB)         // 9216
#define FA_BUFSZ (2 * FA_TILE)           // 18432 (K, V)
#define FA_NSTG 3
#define FA_SMEM (FA_BUF + FA_NSTG * FA_BUFSZ)  // 73728
#define NEG_BIG (-1e30f)
#define ONE_H2  0x3C003C00u              // half2(1.0, 1.0)

__global__ void __launch_bounds__(256, 2)
flash_mma(const __half* __restrict__ qkv, __half* __restrict__ ath)
{
    extern __shared__ char fsm[];
    const uint32_t sb = smem_u32(fsm);

    const int tid  = threadIdx.x;
    const int lane = tid & 31;
    const int wid  = tid >> 5;
    const int b = blockIdx.x >> 4;
    const int h = blockIdx.x & 15;
    const int yy = (int)gridDim.y - 1 - (int)blockIdx.y;   // heavy tiles first
    const int q0 = yy * FA_BQ;
    const int NT = 2 * (yy + 1);
    const int bT = b * T_DIM;
    const int hoff = h * D_DIM;

    auto load_tile = [&](int t, int bufi) {
        const int k0 = t * FA_BC;
        const int row = tid >> 2;
        const int ch2 = (tid & 3) * 2;
        const size_t rb = (size_t)(bT + k0 + row) * N_QKV + hoff;
        const uint32_t tb = sb + FA_BUF + bufi * FA_BUFSZ;
        const uint32_t d = tb + row * FA_LDB + ch2 * 16;
        const __half* skh = qkv + rb + C_DIM;
        const __half* svh = qkv + rb + 2 * C_DIM;
        cp16(d + 0 * FA_TILE,      skh + ch2 * 8);
        cp16(d + 0 * FA_TILE + 16, skh + ch2 * 8 + 8);
        cp16(d + 1 * FA_TILE,      svh + ch2 * 8);
        cp16(d + 1 * FA_TILE + 16, svh + ch2 * 8 + 8);
        CP_COMMIT();
    };

    // ---- issue Q tile load, then prefetch K/V tiles 0 & 1 ----
#pragma unroll
    for (int i = 0; i < 4; ++i) {
        int idx = tid + i * 256;          // 0..1023
        int row = idx >> 3;
        int ch  = idx & 7;
        const __half* src = qkv + (size_t)(bT + q0 + row) * N_QKV + hoff + ch * 8;
        cp16(sb + row * FA_LDB + ch * 16, src);
    }
    CP_COMMIT();
    load_tile(0, 0);
    load_tile(1, 1);          // NT >= 2 always

    CP_WAIT(2);               // Q done; K/V tiles may still be in flight
    __syncthreads();

    uint32_t qf[4][4];
#pragma unroll
    for (int ks = 0; ks < 4; ++ks) {
        uint32_t off = (uint32_t)(wid * 16 + (lane & 15)) * FA_LDB
                     + ks * 32 + (lane >> 4) * 16;
        ldsm4(qf[ks], sb + off);
    }

    float o[8][4];
#pragma unroll
    for (int i = 0; i < 8; ++i)
#pragma unroll
        for (int j = 0; j < 4; ++j) o[i][j] = 0.0f;
    float la[4] = {0.0f, 0.0f, 0.0f, 0.0f};       // l via ones-MMA
    float m0 = NEG_BIG, m1 = NEG_BIG;
    const int qr  = q0 + wid * 16;
    const int qp0 = qr + (lane >> 2);
    const int qp1 = qp0 + 8;
    const uint32_t ones[2] = {ONE_H2, ONE_H2};

    int buf = 0;
    for (int t = 0; t < NT; ++t) {
        if (t + 1 < NT) { CP_WAIT(1); } else { CP_WAIT(0); }
        __syncthreads();
        if (t + 2 < NT) {
            int nb = buf + 2; if (nb >= FA_NSTG) nb -= FA_NSTG;
            load_tile(t + 2, nb);
        }

        const int k0 = t * FA_BC;
        if (k0 <= qr + 15) {
            const uint32_t tb = sb + FA_BUF + buf * FA_BUFSZ;

            float s[8][4];
#pragma unroll
            for (int i = 0; i < 8; ++i)
#pragma unroll
                for (int j = 0; j < 4; ++j) s[i][j] = 0.0f;

#pragma unroll
            for (int ks = 0; ks < 4; ++ks) {
                uint32_t kh[4][4];
#pragma unroll
                for (int np = 0; np < 4; ++np) {
                    uint32_t off = (uint32_t)(np * 16 + (lane & 7)
                                 + ((lane >> 4) & 1) * 8) * FA_LDB
                                 + ks * 32 + ((lane >> 3) & 1) * 16;
                    ldsm4(kh[np], tb + 0 * FA_TILE + off);
                }
#pragma unroll
                for (int ni = 0; ni < 8; ++ni)
                    mma16816(s[ni], qf[ks], &kh[ni >> 1][(ni & 1) * 2]);
            }

            // causal mask (s already in log2 units)
            if (k0 + FA_BC - 1 > qr) {
#pragma unroll
                for (int ni = 0; ni < 8; ++ni) {
                    int kp = k0 + ni * 8 + 2 * (lane & 3);
                    if (kp     > qp0) s[ni][0] = NEG_BIG;
                    if (kp + 1 > qp0) s[ni][1] = NEG_BIG;
                    if (kp     > qp1) s[ni][2] = NEG_BIG;
                    if (kp + 1 > qp1) s[ni][3] = NEG_BIG;
                }
            }

            float mx0 = NEG_BIG, mx1 = NEG_BIG;
#pragma unroll
            for (int ni = 0; ni < 8; ++ni) {
                mx0 = fmaxf(mx0, fmaxf(s[ni][0], s[ni][1]));
                mx1 = fmaxf(mx1, fmaxf(s[ni][2], s[ni][3]));
            }
            mx0 = fmaxf(mx0, __shfl_xor_sync(0xffffffffu, mx0, 1));
            mx0 = fmaxf(mx0, __shfl_xor_sync(0xffffffffu, mx0, 2));
            mx1 = fmaxf(mx1, __shfl_xor_sync(0xffffffffu, mx1, 1));
            mx1 = fmaxf(mx1, __shfl_xor_sync(0xffffffffu, mx1, 2));
            const float m0n = fmaxf(m0, mx0);
            const float m1n = fmaxf(m1, mx1);

            // warp-vote-gated rescale: skip when no row's max changed (exact)
            const bool upd = (m0n > m0) || (m1n > m1);
            if (__any_sync(0xffffffffu, upd)) {
                const float c0 = fexp2(m0 - m0n);   // 1 when unchanged
                const float c1 = fexp2(m1 - m1n);
                la[0] *= c0; la[2] *= c1;
#pragma unroll
                for (int ni = 0; ni < 8; ++ni) {
                    o[ni][0] *= c0; o[ni][1] *= c0;
                    o[ni][2] *= c1; o[ni][3] *= c1;
                }
            }
            m0 = m0n; m1 = m1n;

            // P = exp2(s - m) as fp16 fragments; l += P @ 1; O += P V
#pragma unroll
            for (int ks = 0; ks < 4; ++ks) {
                uint32_t pa[4];
                pa[0] = ex2h2(s[2*ks][0]   - m0, s[2*ks][1]   - m0);
                pa[1] = ex2h2(s[2*ks][2]   - m1, s[2*ks][3]   - m1);
                pa[2] = ex2h2(s[2*ks+1][0] - m0, s[2*ks+1][1] - m0);
                pa[3] = ex2h2(s[2*ks+1][2] - m1, s[2*ks+1][3] - m1);

                mma16816(la, pa, ones);           // row sums

                uint32_t vh[4][4];
#pragma unroll
                for (int nd = 0; nd < 4; ++nd) {
                    uint32_t off = (uint32_t)(ks * 16 + (lane & 15)) * FA_LDB
                                 + nd * 32 + (lane >> 4) * 16;
                    ldsm4t(vh[nd], tb + 1 * FA_TILE + off);
                }
#pragma unroll
                for (int ni = 0; ni < 8; ++ni)
                    mma16816(o[ni], pa, &vh[ni >> 1][(ni & 1) * 2]);
            }
        }
        if (++buf >= FA_NSTG) buf -= FA_NSTG;
    }

    // ---- epilogue: normalize + fp16 store ----
    const float i0 = 1.0f / la[0];
    const float i1 = 1.0f / la[2];

    const size_t r0o = (size_t)(bT + qp0) * C_DIM + hoff + 2 * (lane & 3);
    const size_t r1o = (size_t)(bT + qp1) * C_DIM + hoff + 2 * (lane & 3);
#pragma unroll
    for (int ni = 0; ni < 8; ++ni) {
        *(__half2*)(ath + r0o + ni * 8) =
            __floats2half2_rn(o[ni][0] * i0, o[ni][1] * i0);
        *(__half2*)(ath + r1o + ni * 8) =
            __floats2half2_rn(o[ni][2] * i1, o[ni][3] * i1);
    }
}

// ---------------------------------------------------------------------------
// Launch
// ---------------------------------------------------------------------------
extern "C" void kernel_launch(void* const* d_in, const int* in_sizes, int n_in,
                              void* d_out, int out_size)
{
    const float* x      = (const float*)d_in[0];
    const float* w_attn = (const float*)d_in[1];
    const float* b_attn = (const float*)d_in[2];
    const float* w_proj = (const float*)d_in[3];
    const float* b_proj = (const float*)d_in[4];
    float* out = (float*)d_out;

    void *p_q, *p_xh, *p_wt, *p_wpt, *p_ath;
    cudaGetSymbolAddress(&p_q,   g_qkvh);
    cudaGetSymbolAddress(&p_xh,  g_xh);
    cudaGetSymbolAddress(&p_wt,  g_wt);
    cudaGetSymbolAddress(&p_wpt, g_wpt);
    cudaGetSymbolAddress(&p_ath, g_ath);

    cudaFuncSetAttribute(gemm_1p<true>,
                         cudaFuncAttributeMaxDynamicSharedMemorySize, GEMM_SMEM);
    cudaFuncSetAttribute(gemm_1p<false>,
                         cudaFuncAttributeMaxDynamicSharedMemorySize, GEMM_SMEM);
    cudaFuncSetAttribute(flash_mma,
                         cudaFuncAttributeMaxDynamicSharedMemorySize, FA_SMEM);

    // 1) x -> fp16
    {
        int n = M_ROWS * C_DIM;
        k_half<<<n / 4 / 256, 256>>>(x, (__half*)p_xh, n);
    }
    // 2) transpose weights -> fp16
    {
        dim3 g(N_QKV / 32, C_DIM / 32);
        k_transpose_half<<<g, dim3(32, 8)>>>(w_attn, (__half*)p_wt, C_DIM, N_QKV);
    }
    {
        dim3 g(C_DIM / 32, C_DIM / 32);
        k_transpose_half<<<g, dim3(32, 8)>>>(w_proj, (__half*)p_wpt, C_DIM, C_DIM);
    }
    // 3) qkv = x @ w_attn + b_attn  (1-product fp16; Q scaled by log2e/8)
    {
        dim3 grid(N_QKV / 128, M_ROWS / 128);
        gemm_1p<true><<<grid, 256, GEMM_SMEM>>>(
            (const __half*)p_xh, (const __half*)p_wt, b_attn,
            nullptr, (__half*)p_q, N_QKV, C_DIM);
    }
    // 4) causal MHA (log2-domain flash, fp16 output)
    {
        dim3 grid(B_DIM * H_DIM, T_DIM / FA_BQ);
        flash_mma<<<grid, 256, FA_SMEM>>>((const __half*)p_q, (__half*)p_ath);
    }
    // 5) out = att @ w_proj + b_proj (1-product, fp32 out)
    {
        dim3 grid(C_DIM / 128, M_ROWS / 128);
        gemm_1p<false><<<grid, 256, GEMM_SMEM>>>(
            (const __half*)p_ath, (const __half*)p_wpt, b_proj,
            out, nullptr, C_DIM, C_DIM);
    }
}

// round 17
// speedup vs baseline: 1.2461x; 1.0569x over previous
#include <cuda_runtime.h>
#include <cuda_fp16.h>
#include <math_constants.h>
#include <cstdint>

// ---------------------------------------------------------------------------
// Problem constants
// ---------------------------------------------------------------------------
#define B_DIM 4
#define T_DIM 2048
#define C_DIM 1024
#define H_DIM 16
#define D_DIM 64
#define M_ROWS (B_DIM * T_DIM)       // 8192
#define N_QKV  (3 * C_DIM)           // 3072

// ---------------------------------------------------------------------------
// Device scratch (allocation-free rule)
// ---------------------------------------------------------------------------
__device__ __half g_qkvh[(size_t)M_ROWS * N_QKV];   // qkv fp16 (Q scaled by 0.125*log2e)
__device__ __half g_xh[(size_t)M_ROWS * C_DIM];     // x fp16
__device__ __half g_wt[(size_t)C_DIM * N_QKV];      // w_attn fp16 [1024][3072] (natural)
__device__ __half g_wpt[(size_t)C_DIM * C_DIM];     // w_proj fp16 [1024][1024] (natural)
__device__ __half g_ath[(size_t)M_ROWS * C_DIM];    // attn out fp16

// ---------------------------------------------------------------------------
// Helpers
// ---------------------------------------------------------------------------
__device__ __forceinline__ uint32_t smem_u32(const void* p) {
    uint32_t a;
    asm("{ .reg .u64 t; cvta.to.shared.u64 t, %1; cvt.u32.u64 %0, t; }"
        : "=r"(a) : "l"(p));
    return a;
}

__device__ __forceinline__ void cp16(uint32_t dst, const void* src) {
    asm volatile("cp.async.cg.shared.global [%0], [%1], 16;"
                 :: "r"(dst), "l"(src));
}
#define CP_COMMIT() asm volatile("cp.async.commit_group;" ::: "memory")
#define CP_WAIT(n)  asm volatile("cp.async.wait_group %0;" :: "n"(n) : "memory")

__device__ __forceinline__ void ldsm4(uint32_t* r, uint32_t addr) {
    asm volatile("ldmatrix.sync.aligned.m8n8.x4.shared.b16 {%0,%1,%2,%3}, [%4];"
                 : "=r"(r[0]), "=r"(r[1]), "=r"(r[2]), "=r"(r[3]) : "r"(addr));
}

__device__ __forceinline__ void ldsm4t(uint32_t* r, uint32_t addr) {
    asm volatile("ldmatrix.sync.aligned.m8n8.x4.trans.shared.b16 {%0,%1,%2,%3}, [%4];"
                 : "=r"(r[0]), "=r"(r[1]), "=r"(r[2]), "=r"(r[3]) : "r"(addr));
}

__device__ __forceinline__ void mma16816(float* c, const uint32_t* a,
                                         const uint32_t* b) {
    asm volatile(
        "mma.sync.aligned.m16n8k16.row.col.f32.f16.f16.f32 "
        "{%0,%1,%2,%3}, {%4,%5,%6,%7}, {%8,%9}, {%0,%1,%2,%3};"
        : "+f"(c[0]), "+f"(c[1]), "+f"(c[2]), "+f"(c[3])
        : "r"(a[0]), "r"(a[1]), "r"(a[2]), "r"(a[3]), "r"(b[0]), "r"(b[1]));
}

// exp2 of a float pair -> packed fp16x2 via MUFU ex2.approx.f16x2
__device__ __forceinline__ uint32_t ex2h2(float x, float y) {
    __half2 h = __floats2half2_rn(x, y);
    uint32_t u = *reinterpret_cast<uint32_t*>(&h);
    uint32_t r;
    asm volatile("ex2.approx.f16x2 %0, %1;" : "=r"(r) : "r"(u));
    return r;
}

// exp2 fp32 (single MUFU op)
__device__ __forceinline__ float fexp2(float x) {
    float r;
    asm volatile("ex2.approx.f32 %0, %1;" : "=f"(r) : "f"(x));
    return r;
}

// ---------------------------------------------------------------------------
// Fused prep: fp32 -> fp16 streaming converts for x, w_attn, w_proj (one launch)
// ---------------------------------------------------------------------------
#define N_X  (M_ROWS * C_DIM)        // 8388608
#define N_WA (C_DIM * N_QKV)         // 3145728
#define N_WP (C_DIM * C_DIM)         // 1048576
#define N_CV ((N_X + N_WA + N_WP) / 4)

__global__ void k_convert3(const float* __restrict__ x,
                           const float* __restrict__ wa,
                           const float* __restrict__ wp,
                           __half* __restrict__ xh,
                           __half* __restrict__ wah,
                           __half* __restrict__ wph)
{
    int i = (blockIdx.x * blockDim.x + threadIdx.x) * 4;
    const float* src;
    __half* dst;
    if (i < N_X)                { src = x  + i;               dst = xh  + i; }
    else if (i < N_X + N_WA)    { src = wa + (i - N_X);       dst = wah + (i - N_X); }
    else if (i < N_X + N_WA + N_WP) {
        src = wp + (i - N_X - N_WA);
        dst = wph + (i - N_X - N_WA);
    } else return;
    float4 v = *(const float4*)src;
    *(__half2*)(dst)     = __floats2half2_rn(v.x, v.y);
    *(__half2*)(dst + 2) = __floats2half2_rn(v.z, v.w);
}

// ---------------------------------------------------------------------------
// Unified 1-product HMMA GEMM: C = A @ W + bias, W in natural [K][N] layout.
// B fragments produced by ldmatrix.trans directly from [K][N] smem tiles
// (no pre-transposed weights needed).
// 128x128 CTA tile, BK=32, 8 warps (32x64), 3-stage ring, 2 CTAs/SM.
// QKV_OUT: fp16 out, Q columns (col < C_DIM) scaled by 0.125*log2e;
// else fp32 out.
// ---------------------------------------------------------------------------
#define BKC  32
#define LDSB 80                       // A-tile row stride bytes
#define LDB_B 272                     // B-tile row stride bytes (256 + 16 pad)
#define TILE_A (128 * LDSB)           // 10240
#define TILE_B (BKC * LDB_B)          // 8704
#define STG  (TILE_A + TILE_B)        // 18944 per stage
#define NSTG 3
#define GEMM_SMEM (NSTG * STG)        // 56832 -> 2 CTAs/SM
#define QSCALE 0.18033688f            // 0.125 * log2(e)

template<bool QKV_OUT>
__global__ void __launch_bounds__(256, 2)
gemm_1p(const __half* __restrict__ A, const __half* __restrict__ W,
        const float* __restrict__ bias, float* __restrict__ Cf,
        __half* __restrict__ Ch, int N, int K)
{
    extern __shared__ char sm[];
    const uint32_t sbase = smem_u32(sm);

    const int tid  = threadIdx.x;
    const int lane = tid & 31;
    const int wid  = tid >> 5;
    const int m0 = blockIdx.y * 128;
    const int n0 = blockIdx.x * 128;
    const int wm = (wid & 3) * 32;
    const int wn = (wid >> 2) * 64;

    float acc[2][8][4];
#pragma unroll
    for (int i = 0; i < 2; ++i)
#pragma unroll
        for (int j = 0; j < 8; ++j)
#pragma unroll
            for (int k = 0; k < 4; ++k) acc[i][j][k] = 0.0f;

    // A loader: rows r0, r1 (one 16B slot each at column c0)
    const int r0 = tid >> 2, c0 = tid & 3;
    const int r1 = r0 + 64;
    const __half* pA0 = A + (size_t)(m0 + r0) * K + c0 * 8;
    const __half* pA1 = A + (size_t)(m0 + r1) * K + c0 * 8;
    const uint32_t dA0 = (uint32_t)r0 * LDSB + (uint32_t)c0 * 16;
    const uint32_t dA1 = (uint32_t)r1 * LDSB + (uint32_t)c0 * 16;

    // B loader: [K][N] tile, 32 rows x 16 slots; thread covers slots tid, tid+256
    const int br0 = tid >> 4,  bs0 = tid & 15;
    const int br1 = br0 + 16;
    const __half* pW0 = W + (size_t)br0 * N + n0 + bs0 * 8;
    const __half* pW1 = W + (size_t)br1 * N + n0 + bs0 * 8;
    const uint32_t dB0 = (uint32_t)br0 * LDB_B + (uint32_t)bs0 * 16;
    const uint32_t dB1 = (uint32_t)br1 * LDB_B + (uint32_t)bs0 * 16;

    auto load_chunk = [&](int c, int buf) {
        const int koff = c * BKC;
        const uint32_t db = sbase + buf * STG;
        cp16(db + dA0, pA0 + koff);
        cp16(db + dA1, pA1 + koff);
        cp16(db + TILE_A + dB0, pW0 + (size_t)koff * N);
        cp16(db + TILE_A + dB1, pW1 + (size_t)koff * N);
        CP_COMMIT();
    };

    const int NC = K / BKC;
    load_chunk(0, 0);
    load_chunk(1, 1);

    int buf = 0;
    for (int c = 0; c < NC; ++c) {
        if (c + 1 < NC) { CP_WAIT(1); } else { CP_WAIT(0); }
        __syncthreads();
        if (c + 2 < NC) {
            int nb = buf + 2; if (nb >= NSTG) nb -= NSTG;
            load_chunk(c + 2, nb);
        }

        const uint32_t tb = sbase + buf * STG;
#pragma unroll
        for (int ks = 0; ks < 2; ++ks) {
            uint32_t ah[2][4], bfr[4][4];
#pragma unroll
            for (int mi = 0; mi < 2; ++mi) {
                uint32_t off = (uint32_t)(wm + mi * 16 + (lane & 15)) * LDSB
                             + ks * 32 + (lane >> 4) * 16;
                ldsm4(ah[mi], tb + off);
            }
            // B via ldmatrix.trans from [k][n] rows (flash V-path pattern)
#pragma unroll
            for (int np = 0; np < 4; ++np) {
                uint32_t off = (uint32_t)(ks * 16 + (lane & 15)) * LDB_B
                             + (uint32_t)(wn + np * 16) * 2 + (lane >> 4) * 16;
                ldsm4t(bfr[np], tb + TILE_A + off);
            }
#pragma unroll
            for (int np = 0; np < 4; ++np)
#pragma unroll
                for (int mi = 0; mi < 2; ++mi)
#pragma unroll
                    for (int nj = 0; nj < 2; ++nj)
                        mma16816(acc[mi][2 * np + nj], ah[mi], &bfr[np][nj * 2]);
        }
        if (++buf >= NSTG) buf -= NSTG;
    }

#pragma unroll
    for (int mi = 0; mi < 2; ++mi) {
        const int row = m0 + wm + mi * 16 + (lane >> 2);
#pragma unroll
        for (int ni = 0; ni < 8; ++ni) {
            const int col = n0 + wn + ni * 8 + (lane & 3) * 2;
            float v0x = acc[mi][ni][0] + bias[col];
            float v0y = acc[mi][ni][1] + bias[col + 1];
            float v1x = acc[mi][ni][2] + bias[col];
            float v1y = acc[mi][ni][3] + bias[col + 1];
            if (QKV_OUT) {
                if (col < C_DIM) {     // Q: scale by 1/sqrt(D)*log2e
                    v0x *= QSCALE; v0y *= QSCALE;
                    v1x *= QSCALE; v1y *= QSCALE;
                }
                *(__half2*)(Ch + (size_t)row * N + col) =
                    __floats2half2_rn(v0x, v0y);
                *(__half2*)(Ch + (size_t)(row + 8) * N + col) =
                    __floats2half2_rn(v1x, v1y);
            } else {
                float2 v0, v1;
                v0.x = v0x; v0.y = v0y;
                v1.x = v1x; v1.y = v1y;
                *(float2*)(Cf + (size_t)row * N + col)       = v0;
                *(float2*)(Cf + (size_t)(row + 8) * N + col) = v1;
            }
        }
    }
}

// ---------------------------------------------------------------------------
// HMMA causal flash attention, log2-domain softmax, single-fp16 throughout.
// P via ex2.approx.f16x2; row sums via ones-MMA; fp16 output.
// Warp-vote-gated o-rescale. 3-stage K/V ring, one barrier/tile, 2 CTAs/SM.
// ---------------------------------------------------------------------------
#define FA_BQ   128
#define FA_BC   64
#define FA_LDB  144
#define FA_BUF  (FA_BQ * FA_LDB)         // 18432: Q
#define FA_TILE (FA_BC * FA_LDB)         // 9216
#define FA_BUFSZ (2 * FA_TILE)           // 18432 (K, V)
#define FA_NSTG 3
#define FA_SMEM (FA_BUF + FA_NSTG * FA_BUFSZ)  // 73728
#define NEG_BIG (-1e30f)
#define ONE_H2  0x3C003C00u              // half2(1.0, 1.0)

__global__ void __launch_bounds__(256, 2)
flash_mma(const __half* __restrict__ qkv, __half* __restrict__ ath)
{
    extern __shared__ char fsm[];
    const uint32_t sb = smem_u32(fsm);

    const int tid  = threadIdx.x;
    const int lane = tid & 31;
    const int wid  = tid >> 5;
    const int b = blockIdx.x >> 4;
    const int h = blockIdx.x & 15;
    const int yy = (int)gridDim.y - 1 - (int)blockIdx.y;   // heavy tiles first
    const int q0 = yy * FA_BQ;
    const int NT = 2 * (yy + 1);
    const int bT = b * T_DIM;
    const int hoff = h * D_DIM;

    auto load_tile = [&](int t, int bufi) {
        const int k0 = t * FA_BC;
        const int row = tid >> 2;
        const int ch2 = (tid & 3) * 2;
        const size_t rb = (size_t)(bT + k0 + row) * N_QKV + hoff;
        const uint32_t tb = sb + FA_BUF + bufi * FA_BUFSZ;
        const uint32_t d = tb + row * FA_LDB + ch2 * 16;
        const __half* skh = qkv + rb + C_DIM;
        const __half* svh = qkv + rb + 2 * C_DIM;
        cp16(d + 0 * FA_TILE,      skh + ch2 * 8);
        cp16(d + 0 * FA_TILE + 16, skh + ch2 * 8 + 8);
        cp16(d + 1 * FA_TILE,      svh + ch2 * 8);
        cp16(d + 1 * FA_TILE + 16, svh + ch2 * 8 + 8);
        CP_COMMIT();
    };

    // ---- issue Q tile load, then prefetch K/V tiles 0 & 1 ----
#pragma unroll
    for (int i = 0; i < 4; ++i) {
        int idx = tid + i * 256;          // 0..1023
        int row = idx >> 3;
        int ch  = idx & 7;
        const __half* src = qkv + (size_t)(bT + q0 + row) * N_QKV + hoff + ch * 8;
        cp16(sb + row * FA_LDB + ch * 16, src);
    }
    CP_COMMIT();
    load_tile(0, 0);
    load_tile(1, 1);          // NT >= 2 always

    CP_WAIT(2);               // Q done; K/V tiles may still be in flight
    __syncthreads();

    uint32_t qf[4][4];
#pragma unroll
    for (int ks = 0; ks < 4; ++ks) {
        uint32_t off = (uint32_t)(wid * 16 + (lane & 15)) * FA_LDB
                     + ks * 32 + (lane >> 4) * 16;
        ldsm4(qf[ks], sb + off);
    }

    float o[8][4];
#pragma unroll
    for (int i = 0; i < 8; ++i)
#pragma unroll
        for (int j = 0; j < 4; ++j) o[i][j] = 0.0f;
    float la[4] = {0.0f, 0.0f, 0.0f, 0.0f};       // l via ones-MMA
    float m0 = NEG_BIG, m1 = NEG_BIG;
    const int qr  = q0 + wid * 16;
    const int qp0 = qr + (lane >> 2);
    const int qp1 = qp0 + 8;
    const uint32_t ones[2] = {ONE_H2, ONE_H2};

    int buf = 0;
    for (int t = 0; t < NT; ++t) {
        if (t + 1 < NT) { CP_WAIT(1); } else { CP_WAIT(0); }
        __syncthreads();
        if (t + 2 < NT) {
            int nb = buf + 2; if (nb >= FA_NSTG) nb -= FA_NSTG;
            load_tile(t + 2, nb);
        }

        const int k0 = t * FA_BC;
        if (k0 <= qr + 15) {
            const uint32_t tb = sb + FA_BUF + buf * FA_BUFSZ;

            float s[8][4];
#pragma unroll
            for (int i = 0; i < 8; ++i)
#pragma unroll
                for (int j = 0; j < 4; ++j) s[i][j] = 0.0f;

#pragma unroll
            for (int ks = 0; ks < 4; ++ks) {
                uint32_t kh[4][4];
#pragma unroll
                for (int np = 0; np < 4; ++np) {
                    uint32_t off = (uint32_t)(np * 16 + (lane & 7)
                                 + ((lane >> 4) & 1) * 8) * FA_LDB
                                 + ks * 32 + ((lane >> 3) & 1) * 16;
                    ldsm4(kh[np], tb + 0 * FA_TILE + off);
                }
#pragma unroll
                for (int ni = 0; ni < 8; ++ni)
                    mma16816(s[ni], qf[ks], &kh[ni >> 1][(ni & 1) * 2]);
            }

            // causal mask (s already in log2 units)
            if (k0 + FA_BC - 1 > qr) {
#pragma unroll
                for (int ni = 0; ni < 8; ++ni) {
                    int kp = k0 + ni * 8 + 2 * (lane & 3);
                    if (kp     > qp0) s[ni][0] = NEG_BIG;
                    if (kp + 1 > qp0) s[ni][1] = NEG_BIG;
                    if (kp     > qp1) s[ni][2] = NEG_BIG;
                    if (kp + 1 > qp1) s[ni][3] = NEG_BIG;
                }
            }

            float mx0 = NEG_BIG, mx1 = NEG_BIG;
#pragma unroll
            for (int ni = 0; ni < 8; ++ni) {
                mx0 = fmaxf(mx0, fmaxf(s[ni][0], s[ni][1]));
                mx1 = fmaxf(mx1, fmaxf(s[ni][2], s[ni][3]));
            }
            mx0 = fmaxf(mx0, __shfl_xor_sync(0xffffffffu, mx0, 1));
            mx0 = fmaxf(mx0, __shfl_xor_sync(0xffffffffu, mx0, 2));
            mx1 = fmaxf(mx1, __shfl_xor_sync(0xffffffffu, mx1, 1));
            mx1 = fmaxf(mx1, __shfl_xor_sync(0xffffffffu, mx1, 2));
            const float m0n = fmaxf(m0, mx0);
            const float m1n = fmaxf(m1, mx1);

            // warp-vote-gated rescale: skip when no row's max changed (exact)
            const bool upd = (m0n > m0) || (m1n > m1);
            if (__any_sync(0xffffffffu, upd)) {
                const float c0 = fexp2(m0 - m0n);   // 1 when unchanged
                const float c1 = fexp2(m1 - m1n);
                la[0] *= c0; la[2] *= c1;
#pragma unroll
                for (int ni = 0; ni < 8; ++ni) {
                    o[ni][0] *= c0; o[ni][1] *= c0;
                    o[ni][2] *= c1; o[ni][3] *= c1;
                }
            }
            m0 = m0n; m1 = m1n;

            // P = exp2(s - m) as fp16 fragments; l += P @ 1; O += P V
#pragma unroll
            for (int ks = 0; ks < 4; ++ks) {
                uint32_t pa[4];
                pa[0] = ex2h2(s[2*ks][0]   - m0, s[2*ks][1]   - m0);
                pa[1] = ex2h2(s[2*ks][2]   - m1, s[2*ks][3]   - m1);
                pa[2] = ex2h2(s[2*ks+1][0] - m0, s[2*ks+1][1] - m0);
                pa[3] = ex2h2(s[2*ks+1][2] - m1, s[2*ks+1][3] - m1);

                mma16816(la, pa, ones);           // row sums

                uint32_t vh[4][4];
#pragma unroll
                for (int nd = 0; nd < 4; ++nd) {
                    uint32_t off = (uint32_t)(ks * 16 + (lane & 15)) * FA_LDB
                                 + nd * 32 + (lane >> 4) * 16;
                    ldsm4t(vh[nd], tb + 1 * FA_TILE + off);
                }
#pragma unroll
                for (int ni = 0; ni < 8; ++ni)
                    mma16816(o[ni], pa, &vh[ni >> 1][(ni & 1) * 2]);
            }
        }
        if (++buf >= FA_NSTG) buf -= FA_NSTG;
    }

    // ---- epilogue: normalize + fp16 store ----
    const float i0 = 1.0f / la[0];
    const float i1 = 1.0f / la[2];

    const size_t r0o = (size_t)(bT + qp0) * C_DIM + hoff + 2 * (lane & 3);
    const size_t r1o = (size_t)(bT + qp1) * C_DIM + hoff + 2 * (lane & 3);
#pragma unroll
    for (int ni = 0; ni < 8; ++ni) {
        *(__half2*)(ath + r0o + ni * 8) =
            __floats2half2_rn(o[ni][0] * i0, o[ni][1] * i0);
        *(__half2*)(ath + r1o + ni * 8) =
            __floats2half2_rn(o[ni][2] * i1, o[ni][3] * i1);
    }
}

// ---------------------------------------------------------------------------
// Launch
// ---------------------------------------------------------------------------
extern "C" void kernel_launch(void* const* d_in, const int* in_sizes, int n_in,
                              void* d_out, int out_size)
{
    const float* x      = (const float*)d_in[0];
    const float* w_attn = (const float*)d_in[1];
    const float* b_attn = (const float*)d_in[2];
    const float* w_proj = (const float*)d_in[3];
    const float* b_proj = (const float*)d_in[4];
    float* out = (float*)d_out;

    void *p_q, *p_xh, *p_wt, *p_wpt, *p_ath;
    cudaGetSymbolAddress(&p_q,   g_qkvh);
    cudaGetSymbolAddress(&p_xh,  g_xh);
    cudaGetSymbolAddress(&p_wt,  g_wt);
    cudaGetSymbolAddress(&p_wpt, g_wpt);
    cudaGetSymbolAddress(&p_ath, g_ath);

    cudaFuncSetAttribute(gemm_1p<true>,
                         cudaFuncAttributeMaxDynamicSharedMemorySize, GEMM_SMEM);
    cudaFuncSetAttribute(gemm_1p<false>,
                         cudaFuncAttributeMaxDynamicSharedMemorySize, GEMM_SMEM);
    cudaFuncSetAttribute(flash_mma,
                         cudaFuncAttributeMaxDynamicSharedMemorySize, FA_SMEM);

    // 1) fused fp32 -> fp16 converts (x, w_attn, w_proj) in one launch
    k_convert3<<<(N_CV + 255) / 256, 256>>>(
        x, w_attn, w_proj,
        (__half*)p_xh, (__half*)p_wt, (__half*)p_wpt);

    // 2) qkv = x @ w_attn + b_attn  (1-product fp16; Q scaled by log2e/8)
    {
        dim3 grid(N_QKV / 128, M_ROWS / 128);
        gemm_1p<true><<<grid, 256, GEMM_SMEM>>>(
            (const __half*)p_xh, (const __half*)p_wt, b_attn,
            nullptr, (__half*)p_q, N_QKV, C_DIM);
    }
    // 3) causal MHA (log2-domain flash, fp16 output)
    {
        dim3 grid(B_DIM * H_DIM, T_DIM / FA_BQ);
        flash_mma<<<grid, 256, FA_SMEM>>>((const __half*)p_q, (__half*)p_ath);
    }
    // 4) out = att @ w_proj + b_proj (1-product, fp32 out)
    {
        dim3 grid(C_DIM / 128, M_ROWS / 128);
        gemm_1p<false><<<grid, 256, GEMM_SMEM>>>(
            (const __half*)p_ath, (const __half*)p_wpt, b_proj,
            out, nullptr, C_DIM, C_DIM);
    }
}